// round 15
// baseline (speedup 1.0000x reference)
#include <cuda_runtime.h>
#include <cstdint>
#include <cstddef>

// ---------------------------------------------------------------------------
// DimeNet++ forward. Round 15: R14 + ldmatrix A-fragments over pre-rounded
// tf32 tiles (2 LDSM replace 8 LDS + 8 cvt per warp-k8 in the chains).
// ---------------------------------------------------------------------------

#define E_MAX 120000
#define T_MAX 800000
#define N_MAX 12000
#define H_DIM 128
#define INT_DIM 64
#define BE_DIM 8
#define R_DIM 6
#define SR_DIM 42
#define OE_DIM 256

__device__ float g_rbf [E_MAX * R_DIM];
__device__ float g_xe1 [E_MAX * H_DIM];
__device__ float g_xe2 [E_MAX * H_DIM];
__device__ float g_xji [E_MAX * H_DIM];
__device__ float g_xkjd[E_MAX * INT_DIM];
__device__ float g_agg [E_MAX * INT_DIM];
__device__ float g_sb8a[T_MAX * BE_DIM];
__device__ float g_sb8b[T_MAX * BE_DIM];
__device__ float g_nodes[N_MAX * H_DIM];
__device__ float g_hn1 [N_MAX * OE_DIM];
__device__ float g_hn2 [N_MAX * OE_DIM];
__device__ float g_wr  [1015808];            // tf32-rounded weights

#define WR_KJ    0
#define WR_JI    32768
#define WR_DOWN  65536
#define WR_UP    81920
#define WR_RES   98304
#define WR_LIN   294912
#define WR_OUP   327680
#define WR_OLIN  425984

static inline int cdiv(int a, int b) { return (a + b - 1) / b; }

__device__ __forceinline__ float silu_f(float v) {
    return v / (1.0f + expf(-v));
}
__device__ __forceinline__ uint32_t f2tf32(float f) {
    uint32_t u;
    asm("cvt.rna.tf32.f32 %0, %1;" : "=r"(u) : "f"(f));
    return u;
}
__device__ __forceinline__ float roundtf(float f) {
    return __uint_as_float(f2tf32(f));
}

// ---------------- single-launch weight rounding ------------------------------
#define RND_SEGS 8
struct RndArgs {
    const float4* src[RND_SEGS];
    float4*       dst[RND_SEGS];
    int           n4[RND_SEGS];
};
__global__ void round_all_kernel(RndArgs a) {
    int seg = blockIdx.y;
    int i = blockIdx.x * blockDim.x + threadIdx.x;
    if (i >= a.n4[seg]) return;
    float4 v = a.src[seg][i];
    v.x = roundtf(v.x); v.y = roundtf(v.y);
    v.z = roundtf(v.z); v.w = roundtf(v.w);
    a.dst[seg][i] = v;
}

// ---------------- rbf ------------------------------------------------------
__global__ void rbf_kernel(const float* __restrict__ dist,
                           const float* __restrict__ freq,
                           float* __restrict__ rbf, int E) {
    int e = blockIdx.x * blockDim.x + threadIdx.x;
    if (e >= E) return;
    float d = dist[e] * (1.0f / 5.0f);
    float d2 = d * d;
    float d5 = d2 * d2 * d;
    float env = 1.0f / d - 28.0f * d5 + 48.0f * d5 * d - 21.0f * d5 * d2;
#pragma unroll
    for (int r = 0; r < R_DIM; r++)
        rbf[e * R_DIM + r] = env * sinf(freq[r] * d);
}

// ===========================================================================
// One GEMM stage over a resident 64-row smem tile.
// A: smem, PRE-ROUNDED tf32 (fp32 bit patterns), [64 x K] stride sin.
// A fragments via ldmatrix.m8n8.x4.b16 (1 LDSM = 4 frag regs).
// W: gmem tf32-rounded [K x N]; register-prefetch double-buffered.
// 256 thr, 8 warps (2m x 4n), warp tile 32 x (N/4).
// ===========================================================================
template <int K, int N>
__device__ __forceinline__ void run_mma(
    const float* tin, int sin,
    const float* Wg,
    float* wbuf,
    float acc[2][4][4], int tid)
{
    constexpr int NFRAG = N / 32;
    constexpr int WS    = N + 8;
    constexpr int WCH   = 32 * WS;
    constexpr int C     = K / 32;
    constexpr int WLD   = (32 * N) / 4 / 256;
    const int lane = tid & 31, warp = tid >> 5;
    const int gid = lane >> 2, tig = lane & 3;
    const int wm = (warp & 1) * 32, wn = (warp >> 1) * (N / 4);

    // ldmatrix per-thread address components:
    // sub = lane>>3 selects matrix; row = (sub&1)*8 + (lane&7); col += (sub>>1)*4
    const int sub  = lane >> 3;
    const int arow = wm + ((sub & 1) << 3) + (lane & 7);
    const int acol = (sub >> 1) << 2;
    const uint32_t a_base = (uint32_t)__cvta_generic_to_shared(tin)
                          + (uint32_t)((arow * sin + acol) * 4);
    const uint32_t a_mi_off = (uint32_t)(16 * sin * 4);

#pragma unroll
    for (int i = 0; i < 2; i++)
#pragma unroll
        for (int j = 0; j < 4; j++)
#pragma unroll
            for (int l = 0; l < 4; l++) acc[i][j][l] = 0.0f;

    float4 pw[WLD];
#pragma unroll
    for (int i = 0; i < WLD; i++) {
        int idx = tid + i * 256;
        int n4 = idx & (N / 4 - 1);
        int kr = idx / (N / 4);
        pw[i] = *(const float4*)(Wg + (size_t)kr * N + n4 * 4);
    }

#pragma unroll
    for (int c = 0; c < C; c++) {
        float* buf = wbuf + (c & 1) * WCH;
#pragma unroll
        for (int i = 0; i < WLD; i++) {
            int idx = tid + i * 256;
            int n4 = idx & (N / 4 - 1);
            int kr = idx / (N / 4);
            *(float4*)&buf[kr * WS + n4 * 4] = pw[i];
        }
        __syncthreads();
        if (c + 1 < C) {
#pragma unroll
            for (int i = 0; i < WLD; i++) {
                int idx = tid + i * 256;
                int n4 = idx & (N / 4 - 1);
                int kr = idx / (N / 4);
                pw[i] = *(const float4*)(Wg + (size_t)((c + 1) * 32 + kr) * N + n4 * 4);
            }
        }

#pragma unroll
        for (int k8 = 0; k8 < 4; k8++) {
            uint32_t af[2][4], bf[NFRAG][2];
            const uint32_t koff = (uint32_t)((c * 32 + k8 * 8) * 4);
#pragma unroll
            for (int mi = 0; mi < 2; mi++) {
                uint32_t addr = a_base + koff + mi * a_mi_off;
                asm volatile(
                    "ldmatrix.sync.aligned.m8n8.x4.shared.b16 {%0,%1,%2,%3}, [%4];"
                    : "=r"(af[mi][0]), "=r"(af[mi][1]),
                      "=r"(af[mi][2]), "=r"(af[mi][3])
                    : "r"(addr));
            }
#pragma unroll
            for (int ni = 0; ni < NFRAG; ni++) {
                int nn = wn + ni * 8 + gid;
                bf[ni][0] = __float_as_uint(buf[(k8 * 8 + tig) * WS + nn]);
                bf[ni][1] = __float_as_uint(buf[(k8 * 8 + tig + 4) * WS + nn]);
            }
#pragma unroll
            for (int mi = 0; mi < 2; mi++)
#pragma unroll
                for (int ni = 0; ni < NFRAG; ni++)
                    asm volatile(
                        "mma.sync.aligned.m16n8k8.row.col.f32.tf32.tf32.f32 "
                        "{%0,%1,%2,%3}, {%4,%5,%6,%7}, {%8,%9}, {%0,%1,%2,%3};"
                        : "+f"(acc[mi][ni][0]), "+f"(acc[mi][ni][1]),
                          "+f"(acc[mi][ni][2]), "+f"(acc[mi][ni][3])
                        : "r"(af[mi][0]), "r"(af[mi][1]),
                          "r"(af[mi][2]), "r"(af[mi][3]),
                          "r"(bf[ni][0]), "r"(bf[ni][1]));
        }
    }
    __syncthreads();
}

// tile strides / smem offsets (fp32 words), BM=64
#define TS128 132
#define TS64  68
#define SM_TA 0
#define SM_TT 8448
#define SM_WB 16896
#define SM_T8 25600
#define SM_W2 26112
#define SM_WOR 27136
#define SMEM_PRE  (27904 * 4)
#define SMEM_POST (26368 * 4)

// epilogue iteration (variadic), BM=64
#define EPI_LOOP(NF, WN_SC, ...)                                               \
    {                                                                          \
        const int wm_ = (warp & 1) * 32;                                       \
        const int wn_ = (warp >> 1) * (WN_SC);                                 \
        _Pragma("unroll")                                                      \
        for (int mi = 0; mi < 2; mi++) {                                       \
            _Pragma("unroll")                                                  \
            for (int rr = 0; rr < 2; rr++) {                                   \
                const int ml = wm_ + mi * 16 + gid + rr * 8;                   \
                _Pragma("unroll")                                              \
                for (int ni = 0; ni < (NF); ni++) {                            \
                    const int n = wn_ + ni * 8 + tig * 2;                      \
                    float v0 = acc[mi][ni][rr * 2 + 0];                        \
                    float v1 = acc[mi][ni][rr * 2 + 1];                        \
                    __VA_ARGS__                                                \
                }                                                              \
            }                                                                  \
        }                                                                      \
    }

// gather from a smem tile (64 rows) into nodes via float4 atomics.
__device__ __forceinline__ void tile_gather(
    const float* tile, int ts, const float* wor,
    const float* __restrict__ rbf, const int* __restrict__ edge_i,
    float4* __restrict__ nodes, int bm, int E, int warp, int lane)
{
    for (int rr = warp; rr < 64; rr += 8) {
        int gm = bm + rr;
        if (gm >= E) continue;
        int ni = edge_i[gm];
        float rv[R_DIM];
#pragma unroll
        for (int r = 0; r < R_DIM; r++) rv[r] = rbf[gm * R_DIM + r];
        int c = lane * 4;
        float s0 = 0.f, s1 = 0.f, s2 = 0.f, s3 = 0.f;
#pragma unroll
        for (int r = 0; r < R_DIM; r++) {
            const float* w = wor + r * H_DIM + c;
            s0 += rv[r] * w[0];
            s1 += rv[r] * w[1];
            s2 += rv[r] * w[2];
            s3 += rv[r] * w[3];
        }
        const float* tv = tile + (size_t)rr * ts + c;
        float4 m = make_float4(s0 * tv[0], s1 * tv[1], s2 * tv[2], s3 * tv[3]);
        atomicAdd(&nodes[(size_t)ni * (H_DIM / 4) + lane], m);
    }
}

// ===========================================================================
// pre_chain — tiles pre-rounded tf32
// ===========================================================================
__global__ __launch_bounds__(256)
void pre_chain(const float* __restrict__ xe, const float* __restrict__ rbf,
               const float* __restrict__ Wji, const float* __restrict__ bji,
               const float* __restrict__ Wkj, const float* __restrict__ bkj,
               const float* __restrict__ W1,  const float* __restrict__ W2,
               const float* __restrict__ Wdown,
               const float* __restrict__ Wo_r,
               const int* __restrict__ edge_i,
               float4* __restrict__ nodes,
               float* __restrict__ xji, float* __restrict__ xkjd, int E) {
    extern __shared__ float sm[];
    float* tileA = sm + SM_TA;
    float* tileT = sm + SM_TT;
    float* wbuf  = sm + SM_WB;
    float* t8    = sm + SM_T8;
    float* w2s   = sm + SM_W2;
    float* wor   = sm + SM_WOR;

    const int tid  = threadIdx.x;
    const int lane = tid & 31, warp = tid >> 5;
    const int gid  = lane >> 2, tig = lane & 3;
    const int bm   = blockIdx.x * 64;

#pragma unroll
    for (int i = 0; i < 8; i++) {
        int idx = tid + i * 256;
        int row = idx >> 5, c4 = idx & 31;
        int gm = bm + row;
        float4 v = (gm < E) ? *(const float4*)(xe + (size_t)gm * H_DIM + c4 * 4)
                            : make_float4(0.f, 0.f, 0.f, 0.f);
        v.x = roundtf(v.x); v.y = roundtf(v.y);
        v.z = roundtf(v.z); v.w = roundtf(v.w);
        *(float4*)&tileA[row * TS128 + c4 * 4] = v;
    }
    for (int i = tid; i < BE_DIM * H_DIM; i += 256) w2s[i] = W2[i];
    if (Wo_r) {
        for (int i = tid; i < R_DIM * H_DIM; i += 256) wor[i] = Wo_r[i];
    }
    if (tid < 64) {
        int gm = bm + tid;
        float rv[R_DIM];
#pragma unroll
        for (int r = 0; r < R_DIM; r++) rv[r] = (gm < E) ? rbf[gm * R_DIM + r] : 0.f;
#pragma unroll
        for (int j = 0; j < BE_DIM; j++) {
            float s = 0.f;
#pragma unroll
            for (int r = 0; r < R_DIM; r++) s += rv[r] * W1[r * BE_DIM + j];
            t8[tid * BE_DIM + j] = s;
        }
    }
    __syncthreads();

    if (Wo_r) {
        tile_gather(tileA, TS128, wor, rbf, edge_i, nodes, bm, E, warp, lane);
    }

    float acc[2][4][4];

    // S1: xji = round(silu(xe@Wji + bji)) -> gmem
    run_mma<128, 128>(tileA, TS128, Wji, wbuf, acc, tid);
    EPI_LOOP(4, 32, {
        int gm = bm + ml;
        if (gm < E) {
            v0 = roundtf(silu_f(v0 + bji[n]));
            v1 = roundtf(silu_f(v1 + bji[n + 1]));
            *(float2*)(xji + (size_t)gm * H_DIM + n) = make_float2(v0, v1);
        }
    })

    // S2: xk = round(silu(xe@Wkj + bkj) * rb) -> tileT
    run_mma<128, 128>(tileA, TS128, Wkj, wbuf, acc, tid);
    EPI_LOOP(4, 32, {
        v0 = silu_f(v0 + bkj[n]);
        v1 = silu_f(v1 + bkj[n + 1]);
        float rb0 = 0.f;
        float rb1 = 0.f;
#pragma unroll
        for (int j = 0; j < BE_DIM; j++) {
            float tj = t8[ml * BE_DIM + j];
            rb0 += tj * w2s[j * H_DIM + n];
            rb1 += tj * w2s[j * H_DIM + n + 1];
        }
        tileT[ml * TS128 + n]     = roundtf(v0 * rb0);
        tileT[ml * TS128 + n + 1] = roundtf(v1 * rb1);
    })
    __syncthreads();

    // S3: xkjd = round(silu(xk@Wdown)) -> gmem, N=64
    run_mma<128, 64>(tileT, TS128, Wdown, wbuf, acc, tid);
    EPI_LOOP(2, 16, {
        int gm = bm + ml;
        if (gm < E) {
            v0 = roundtf(silu_f(v0));
            v1 = roundtf(silu_f(v1));
            *(float2*)(xkjd + (size_t)gm * INT_DIM + n) = make_float2(v0, v1);
        }
    })
}

// ===========================================================================
// post_chain — tiles pre-rounded tf32; fused gather for next output block
// ===========================================================================
__global__ __launch_bounds__(256)
void post_chain(const float* __restrict__ agg, const float* __restrict__ xji,
                const float* __restrict__ xeOld,
                const float* __restrict__ Wup,
                const float* __restrict__ Wr0a, const float* __restrict__ br0a,
                const float* __restrict__ Wr0b, const float* __restrict__ br0b,
                const float* __restrict__ Wlin, const float* __restrict__ blin,
                const float* __restrict__ Wr1a, const float* __restrict__ br1a,
                const float* __restrict__ Wr1b, const float* __restrict__ br1b,
                const float* __restrict__ Wr2a, const float* __restrict__ br2a,
                const float* __restrict__ Wr2b, const float* __restrict__ br2b,
                const float* __restrict__ rbfp,
                const float* __restrict__ Wo_r,
                const int* __restrict__ edge_i,
                float4* __restrict__ nodes,
                float* __restrict__ xeNew, int E) {
    extern __shared__ float sm[];
    float* tileA = sm + SM_TA;
    float* tileT = sm + SM_TT;
    float* wbuf  = sm + SM_WB;
    float* wor   = sm + SM_T8;

    const int tid  = threadIdx.x;
    const int lane = tid & 31, warp = tid >> 5;
    const int gid  = lane >> 2, tig = lane & 3;
    const int bm   = blockIdx.x * 64;

#pragma unroll
    for (int i = 0; i < 4; i++) {
        int idx = tid + i * 256;
        int row = idx >> 4, c4 = idx & 15;
        int gm = bm + row;
        float4 v = (gm < E) ? *(const float4*)(agg + (size_t)gm * INT_DIM + c4 * 4)
                            : make_float4(0.f, 0.f, 0.f, 0.f);
        v.x = roundtf(v.x); v.y = roundtf(v.y);
        v.z = roundtf(v.z); v.w = roundtf(v.w);
        *(float4*)&tileT[row * TS64 + c4 * 4] = v;
    }
    for (int i = tid; i < R_DIM * H_DIM; i += 256) wor[i] = Wo_r[i];
    __syncthreads();

    float acc[2][4][4];

    // up: tileA = round(xji + silu(agg@Wup))
    run_mma<64, 128>(tileT, TS64, Wup, wbuf, acc, tid);
    EPI_LOOP(4, 32, {
        int gm = bm + ml;
        float2 p = (gm < E) ? *(const float2*)(xji + (size_t)gm * H_DIM + n)
                            : make_float2(0.f, 0.f);
        tileA[ml * TS128 + n]     = roundtf(p.x + silu_f(v0));
        tileA[ml * TS128 + n + 1] = roundtf(p.y + silu_f(v1));
    })
    __syncthreads();

    // res0a
    run_mma<128, 128>(tileA, TS128, Wr0a, wbuf, acc, tid);
    EPI_LOOP(4, 32, {
        tileT[ml * TS128 + n]     = roundtf(silu_f(v0 + br0a[n]));
        tileT[ml * TS128 + n + 1] = roundtf(silu_f(v1 + br0a[n + 1]));
    })
    __syncthreads();

    // res0b
    run_mma<128, 128>(tileT, TS128, Wr0b, wbuf, acc, tid);
    EPI_LOOP(4, 32, {
        tileA[ml * TS128 + n]     = roundtf(tileA[ml * TS128 + n]     + silu_f(v0 + br0b[n]));
        tileA[ml * TS128 + n + 1] = roundtf(tileA[ml * TS128 + n + 1] + silu_f(v1 + br0b[n + 1]));
    })
    __syncthreads();

    // lin+skip
    run_mma<128, 128>(tileA, TS128, Wlin, wbuf, acc, tid);
    EPI_LOOP(4, 32, {
        int gm = bm + ml;
        float2 p = (gm < E) ? *(const float2*)(xeOld + (size_t)gm * H_DIM + n)
                            : make_float2(0.f, 0.f);
        tileT[ml * TS128 + n]     = roundtf(silu_f(v0 + blin[n]) + p.x);
        tileT[ml * TS128 + n + 1] = roundtf(silu_f(v1 + blin[n + 1]) + p.y);
    })
    __syncthreads();

    // res1a
    run_mma<128, 128>(tileT, TS128, Wr1a, wbuf, acc, tid);
    EPI_LOOP(4, 32, {
        tileA[ml * TS128 + n]     = roundtf(silu_f(v0 + br1a[n]));
        tileA[ml * TS128 + n + 1] = roundtf(silu_f(v1 + br1a[n + 1]));
    })
    __syncthreads();

    // res1b
    run_mma<128, 128>(tileA, TS128, Wr1b, wbuf, acc, tid);
    EPI_LOOP(4, 32, {
        tileT[ml * TS128 + n]     = roundtf(tileT[ml * TS128 + n]     + silu_f(v0 + br1b[n]));
        tileT[ml * TS128 + n + 1] = roundtf(tileT[ml * TS128 + n + 1] + silu_f(v1 + br1b[n + 1]));
    })
    __syncthreads();

    // res2a
    run_mma<128, 128>(tileT, TS128, Wr2a, wbuf, acc, tid);
    EPI_LOOP(4, 32, {
        tileA[ml * TS128 + n]     = roundtf(silu_f(v0 + br2a[n]));
        tileA[ml * TS128 + n + 1] = roundtf(silu_f(v1 + br2a[n + 1]));
    })
    __syncthreads();

    // res2b -> xeNew (gmem) and tileT (for fused gather)
    run_mma<128, 128>(tileA, TS128, Wr2b, wbuf, acc, tid);
    EPI_LOOP(4, 32, {
        int gm = bm + ml;
        v0 = roundtf(tileT[ml * TS128 + n]     + silu_f(v0 + br2b[n]));
        v1 = roundtf(tileT[ml * TS128 + n + 1] + silu_f(v1 + br2b[n + 1]));
        tileT[ml * TS128 + n]     = v0;
        tileT[ml * TS128 + n + 1] = v1;
        if (gm < E) {
            *(float2*)(xeNew + (size_t)gm * H_DIM + n) = make_float2(v0, v1);
        }
    })
    __syncthreads();

    tile_gather(tileT, TS128, wor, rbfp, edge_i, nodes, bm, E, warp, lane);
}

// ---------------- tf32 GEMM (node path), cp.async pipeline ------------------
#define TBM 128
#define TBK 32

template <int BN_, bool SILU>
__global__ __launch_bounds__(256, 2)
void tgemm(const float* __restrict__ A, const float* __restrict__ W,
           const float* __restrict__ bias,
           float* __restrict__ C, int M, int K, int N) {
    constexpr int NFRAG   = BN_ / 32;
    constexpr int WSTRIDE = BN_ + 8;
    constexpr int ASZ     = TBM * 36;
    constexpr int WSZ     = TBK * WSTRIDE;
    constexpr int WLD     = (TBK * BN_) / 4 / 256;

    extern __shared__ uint32_t smw[];
    const uint32_t smem_u32 = (uint32_t)__cvta_generic_to_shared(smw);

    const int bm   = blockIdx.y * TBM;
    const int bn   = blockIdx.x * BN_;
    const int tid  = threadIdx.x;
    const int lane = tid & 31;
    const int warp = tid >> 5;
    const int gid  = lane >> 2;
    const int tig  = lane & 3;
    const int wm   = (warp & 1) * 64;
    const int wn   = (warp >> 1) * (BN_ / 4);

    float acc[4][NFRAG][4];
#pragma unroll
    for (int i = 0; i < 4; i++)
#pragma unroll
        for (int j = 0; j < NFRAG; j++)
#pragma unroll
            for (int l = 0; l < 4; l++) acc[i][j][l] = 0.0f;

    const int nk = K / TBK;

#define ISSUE(KT, S)                                                            \
    {                                                                           \
        _Pragma("unroll")                                                       \
        for (int i = 0; i < 4; i++) {                                           \
            int idx = tid + i * 256;                                            \
            int row = idx >> 3, c4 = idx & 7;                                   \
            int gm = bm + row;                                                  \
            int ok = (gm < M);                                                  \
            const float* src = A + (size_t)(ok ? gm : 0) * K + (KT) * TBK + c4 * 4; \
            uint32_t dst = smem_u32 + ((S) * ASZ + row * 36 + c4 * 4) * 4;      \
            int p = ok ? 16 : 0;                                                \
            asm volatile("cp.async.cg.shared.global [%0], [%1], 16, %2;\n"      \
                         :: "r"(dst), "l"(src), "r"(p));                        \
        }                                                                       \
        _Pragma("unroll")                                                       \
        for (int i = 0; i < WLD; i++) {                                         \
            int idx = tid + i * 256;                                            \
            int c4 = idx & (BN_ / 4 - 1);                                       \
            int kr = idx / (BN_ / 4);                                           \
            const float* src = W + (size_t)((KT) * TBK + kr) * N + bn + c4 * 4; \
            uint32_t dst = smem_u32 + (2 * ASZ + (S) * WSZ + kr * WSTRIDE + c4 * 4) * 4; \
            asm volatile("cp.async.cg.shared.global [%0], [%1], 16;\n"          \
                         :: "r"(dst), "l"(src));                                \
        }                                                                       \
        asm volatile("cp.async.commit_group;\n" ::: "memory");                  \
    }

    ISSUE(0, 0);

    for (int kt = 0; kt < nk; kt++) {
        const int cur = kt & 1;
        if (kt + 1 < nk) {
            ISSUE(kt + 1, (kt + 1) & 1);
            asm volatile("cp.async.wait_group 1;\n" ::: "memory");
        } else {
            asm volatile("cp.async.wait_group 0;\n" ::: "memory");
        }
        __syncthreads();

        const uint32_t* Ab = smw + cur * ASZ;
        const uint32_t* Wb = smw + 2 * ASZ + cur * WSZ;
#pragma unroll
        for (int k8 = 0; k8 < TBK / 8; k8++) {
            uint32_t af[4][4], bf[NFRAG][2];
#pragma unroll
            for (int mi = 0; mi < 4; mi++) {
                int r = wm + mi * 16 + gid;
                af[mi][0] = f2tf32(__uint_as_float(Ab[(size_t)r * 36 + k8 * 8 + tig]));
                af[mi][1] = f2tf32(__uint_as_float(Ab[(size_t)(r + 8) * 36 + k8 * 8 + tig]));
                af[mi][2] = f2tf32(__uint_as_float(Ab[(size_t)r * 36 + k8 * 8 + tig + 4]));
                af[mi][3] = f2tf32(__uint_as_float(Ab[(size_t)(r + 8) * 36 + k8 * 8 + tig + 4]));
            }
#pragma unroll
            for (int ni = 0; ni < NFRAG; ni++) {
                int n = wn + ni * 8 + gid;
                bf[ni][0] = Wb[(size_t)(k8 * 8 + tig) * WSTRIDE + n];
                bf[ni][1] = Wb[(size_t)(k8 * 8 + tig + 4) * WSTRIDE + n];
            }
#pragma unroll
            for (int mi = 0; mi < 4; mi++)
#pragma unroll
                for (int ni = 0; ni < NFRAG; ni++)
                    asm volatile(
                        "mma.sync.aligned.m16n8k8.row.col.f32.tf32.tf32.f32 "
                        "{%0,%1,%2,%3}, {%4,%5,%6,%7}, {%8,%9}, {%0,%1,%2,%3};"
                        : "+f"(acc[mi][ni][0]), "+f"(acc[mi][ni][1]),
                          "+f"(acc[mi][ni][2]), "+f"(acc[mi][ni][3])
                        : "r"(af[mi][0]), "r"(af[mi][1]),
                          "r"(af[mi][2]), "r"(af[mi][3]),
                          "r"(bf[ni][0]), "r"(bf[ni][1]));
        }
        __syncthreads();
    }

#pragma unroll
    for (int mi = 0; mi < 4; mi++) {
#pragma unroll
        for (int rr = 0; rr < 2; rr++) {
            int m = bm + wm + mi * 16 + gid + rr * 8;
            if (m >= M) continue;
#pragma unroll
            for (int ni = 0; ni < NFRAG; ni++) {
                int n = bn + wn + ni * 8 + tig * 2;
                float v0 = acc[mi][ni][rr * 2 + 0];
                float v1 = acc[mi][ni][rr * 2 + 1];
                if (bias) { v0 += bias[n]; v1 += bias[n + 1]; }
                if (SILU) { v0 = silu_f(v0); v1 = silu_f(v1); }
                *(float2*)(C + (size_t)m * N + n) = make_float2(v0, v1);
            }
        }
    }
#undef ISSUE
}

#define SMEM_T128 ((2 * TBM * 36 + 2 * TBK * (128 + 8)) * 4)

// ---------------- dual sb8 --------------------------------------------------
__global__ void sb8_dual_kernel(const float* __restrict__ sbf,
                                const float* __restrict__ W1a,
                                const float* __restrict__ W1b,
                                float* __restrict__ sb8a,
                                float* __restrict__ sb8b, int T) {
    __shared__ float Wa[SR_DIM * BE_DIM];
    __shared__ float Wb[SR_DIM * BE_DIM];
    for (int i = threadIdx.x; i < SR_DIM * BE_DIM; i += blockDim.x) {
        Wa[i] = W1a[i];
        Wb[i] = W1b[i];
    }
    __syncthreads();
    int t = blockIdx.x * blockDim.x + threadIdx.x;
    if (t >= T) return;
    const float2* row = (const float2*)(sbf + (size_t)t * SR_DIM);
    float ta[BE_DIM] = {};
    float tb[BE_DIM] = {};
#pragma unroll
    for (int r2 = 0; r2 < SR_DIM / 2; r2++) {
        float2 v = row[r2];
        int r = r2 * 2;
#pragma unroll
        for (int j = 0; j < BE_DIM; j++) {
            ta[j] += v.x * Wa[r * BE_DIM + j] + v.y * Wa[(r + 1) * BE_DIM + j];
            tb[j] += v.x * Wb[r * BE_DIM + j] + v.y * Wb[(r + 1) * BE_DIM + j];
        }
    }
    float4* oa = (float4*)(sb8a + (size_t)t * BE_DIM);
    oa[0] = make_float4(ta[0], ta[1], ta[2], ta[3]);
    oa[1] = make_float4(ta[4], ta[5], ta[6], ta[7]);
    float4* ob = (float4*)(sb8b + (size_t)t * BE_DIM);
    ob[0] = make_float4(tb[0], tb[1], tb[2], tb[3]);
    ob[1] = make_float4(tb[4], tb[5], tb[6], tb[7]);
}

// ---------------- triplet scatter ------------------------------------------
__global__ void triplet_kernel(const float* __restrict__ sb8,
                               const float* __restrict__ W2,
                               const float* __restrict__ xkd,
                               const int* __restrict__ idx_kj,
                               const int* __restrict__ idx_ji,
                               float4* __restrict__ agg, int T) {
    __shared__ float W2s[BE_DIM * INT_DIM];
    for (int i = threadIdx.x; i < BE_DIM * INT_DIM; i += blockDim.x) W2s[i] = W2[i];
    __syncthreads();
    int warp = threadIdx.x >> 5, lane = threadIdx.x & 31;
    int t = (blockIdx.x * (blockDim.x >> 5) + warp) * 2 + (lane >> 4);
    if (t >= T) return;
    int l16 = lane & 15;
    int ik = idx_kj[t];
    int ij = idx_ji[t];
    float4 sA = *(const float4*)(sb8 + (size_t)t * BE_DIM);
    float4 sB = *(const float4*)(sb8 + (size_t)t * BE_DIM + 4);
    float sv[8] = {sA.x, sA.y, sA.z, sA.w, sB.x, sB.y, sB.z, sB.w};
    float4 v = make_float4(0.f, 0.f, 0.f, 0.f);
#pragma unroll
    for (int i = 0; i < BE_DIM; i++) {
        const float* wrow = W2s + i * INT_DIM + l16 * 4;
        v.x += sv[i] * wrow[0];
        v.y += sv[i] * wrow[1];
        v.z += sv[i] * wrow[2];
        v.w += sv[i] * wrow[3];
    }
    float4 x = *(const float4*)(xkd + (size_t)ik * INT_DIM + l16 * 4);
    float4 m = make_float4(x.x * v.x, x.y * v.y, x.z * v.z, x.w * v.w);
    atomicAdd(&agg[(size_t)ij * (INT_DIM / 4) + l16], m);
}

// ---------------- final projection -----------------------------------------
__global__ void out_final_kernel(const float* __restrict__ hn,
                                 const float* __restrict__ Wout,
                                 float* __restrict__ out, int Nn, int accumulate) {
    int warp = threadIdx.x >> 5, lane = threadIdx.x & 31;
    int n = blockIdx.x * (blockDim.x >> 5) + warp;
    if (n >= Nn) return;
    float s = 0.0f;
#pragma unroll
    for (int k = lane; k < OE_DIM; k += 32) s += hn[(size_t)n * OE_DIM + k] * Wout[k];
#pragma unroll
    for (int o = 16; o > 0; o >>= 1) s += __shfl_xor_sync(0xffffffffu, s, o);
    if (lane == 0) {
        if (accumulate) out[n] += s;
        else            out[n] = s;
    }
}

// ---------------------------------------------------------------------------
extern "C" void kernel_launch(void* const* d_in, const int* in_sizes, int n_in,
                              void* d_out, int out_size) {
    const float* x       = (const float*)d_in[0];
    const float* dist    = (const float*)d_in[1];
    const float* freq    = (const float*)d_in[2];
    const float* sbf     = (const float*)d_in[3];
    const int*   idx_kj  = (const int*)d_in[4];
    const int*   idx_ji  = (const int*)d_in[5];
    const int*   edge_i  = (const int*)d_in[6];
    const float* Wi_rbf1 = (const float*)d_in[8];
    const float* Wi_rbf2 = (const float*)d_in[9];
    const float* Wi_sbf1 = (const float*)d_in[10];
    const float* Wi_sbf2 = (const float*)d_in[11];
    const float* Wi_kj   = (const float*)d_in[12];
    const float* bi_kj   = (const float*)d_in[13];
    const float* Wi_ji   = (const float*)d_in[14];
    const float* bi_ji   = (const float*)d_in[15];
    const float* Wi_down = (const float*)d_in[16];
    const float* Wi_up   = (const float*)d_in[17];
    const float* Wi_res  = (const float*)d_in[18];
    const float* bi_res  = (const float*)d_in[19];
    const float* Wi_lin  = (const float*)d_in[20];
    const float* bi_lin  = (const float*)d_in[21];
    const float* Wo_rbf  = (const float*)d_in[22];
    const float* Wo_up   = (const float*)d_in[23];
    const float* bo_up   = (const float*)d_in[24];
    const float* Wo_lin  = (const float*)d_in[25];
    const float* bo_lin  = (const float*)d_in[26];
    const float* Wo_out  = (const float*)d_in[27];

    const int E  = in_sizes[1];
    const int T  = in_sizes[4];
    const int Nn = out_size;
    float* out = (float*)d_out;

    float *p_rbf, *p_xe1, *p_xe2, *p_xji, *p_xkjd, *p_agg, *p_sb8a, *p_sb8b;
    float *p_nodes, *p_hn1, *p_hn2, *p_wr;
    cudaGetSymbolAddress((void**)&p_rbf,  g_rbf);
    cudaGetSymbolAddress((void**)&p_xe1,  g_xe1);
    cudaGetSymbolAddress((void**)&p_xe2,  g_xe2);
    cudaGetSymbolAddress((void**)&p_xji,  g_xji);
    cudaGetSymbolAddress((void**)&p_xkjd, g_xkjd);
    cudaGetSymbolAddress((void**)&p_agg,  g_agg);
    cudaGetSymbolAddress((void**)&p_sb8a, g_sb8a);
    cudaGetSymbolAddress((void**)&p_sb8b, g_sb8b);
    cudaGetSymbolAddress((void**)&p_nodes,g_nodes);
    cudaGetSymbolAddress((void**)&p_hn1,  g_hn1);
    cudaGetSymbolAddress((void**)&p_hn2,  g_hn2);
    cudaGetSymbolAddress((void**)&p_wr,   g_wr);

    cudaFuncSetAttribute(pre_chain,  cudaFuncAttributeMaxDynamicSharedMemorySize, SMEM_PRE);
    cudaFuncSetAttribute(post_chain, cudaFuncAttributeMaxDynamicSharedMemorySize, SMEM_POST);
    cudaFuncSetAttribute(tgemm<128, true >, cudaFuncAttributeMaxDynamicSharedMemorySize, SMEM_T128);
    cudaFuncSetAttribute(tgemm<128, false>, cudaFuncAttributeMaxDynamicSharedMemorySize, SMEM_T128);

    // ---- single-launch weight rounding ----
    RndArgs ra;
    const float* srcs[RND_SEGS] = {Wi_kj, Wi_ji, Wi_down, Wi_up, Wi_res, Wi_lin, Wo_up, Wo_lin};
    const int    offs[RND_SEGS] = {WR_KJ, WR_JI, WR_DOWN, WR_UP, WR_RES, WR_LIN, WR_OUP, WR_OLIN};
    const int    cnts[RND_SEGS] = {
        2 * H_DIM * H_DIM, 2 * H_DIM * H_DIM, 2 * H_DIM * INT_DIM,
        2 * INT_DIM * H_DIM, 2 * 3 * 2 * H_DIM * H_DIM, 2 * H_DIM * H_DIM,
        3 * H_DIM * OE_DIM, 3 * 3 * OE_DIM * OE_DIM};
    int max_n4 = 0;
    for (int s = 0; s < RND_SEGS; s++) {
        ra.src[s] = (const float4*)srcs[s];
        ra.dst[s] = (float4*)(p_wr + offs[s]);
        ra.n4[s]  = cnts[s] / 4;
        if (ra.n4[s] > max_n4) max_n4 = ra.n4[s];
    }
    round_all_kernel<<<dim3(cdiv(max_n4, 256), RND_SEGS), 256>>>(ra);

    const float* wr_kj   = p_wr + WR_KJ;
    const float* wr_ji   = p_wr + WR_JI;
    const float* wr_down = p_wr + WR_DOWN;
    const float* wr_up   = p_wr + WR_UP;
    const float* wr_res  = p_wr + WR_RES;
    const float* wr_lin  = p_wr + WR_LIN;
    const float* wr_oup  = p_wr + WR_OUP;
    const float* wr_olin = p_wr + WR_OLIN;

    const int nTiles = cdiv(E, 64);
    const dim3 gN256(OE_DIM / 128, cdiv(Nn, TBM));

    rbf_kernel<<<cdiv(E, 256), 256>>>(dist, freq, p_rbf, E);
    sb8_dual_kernel<<<cdiv(T, 256), 256>>>(sbf,
        Wi_sbf1, Wi_sbf1 + (size_t)SR_DIM * BE_DIM, p_sb8a, p_sb8b, T);

    auto run_output_mlp = [&](int b, int acc) {
        tgemm<128, false><<<gN256, 256, SMEM_T128>>>(
            p_nodes, wr_oup + (size_t)b * H_DIM * OE_DIM, bo_up + (size_t)b * OE_DIM,
            p_hn1, Nn, H_DIM, OE_DIM);
        for (int l = 0; l < 3; l++) {
            const float* src = (l & 1) ? p_hn2 : p_hn1;
            float*       dst = (l & 1) ? p_hn1 : p_hn2;
            tgemm<128, true><<<gN256, 256, SMEM_T128>>>(
                src, wr_olin + ((size_t)b * 3 + l) * OE_DIM * OE_DIM,
                bo_lin + ((size_t)b * 3 + l) * OE_DIM, dst, Nn, OE_DIM, OE_DIM);
        }
        out_final_kernel<<<cdiv(Nn, 8), 256>>>(p_hn2, Wo_out + (size_t)b * OE_DIM,
                                               out, Nn, acc);
    };

    const float* xe = x;
    float* xeBufs[2] = {p_xe1, p_xe2};
    float* sb8Bufs[2] = {p_sb8a, p_sb8b};

    for (int b = 0; b < 2; b++) {
        const size_t oHH = (size_t)b * H_DIM * H_DIM;
        const size_t oH  = (size_t)b * H_DIM;

        if (b == 0) cudaMemsetAsync(p_nodes, 0, (size_t)Nn * H_DIM * sizeof(float));
        pre_chain<<<nTiles, 256, SMEM_PRE>>>(
            xe, p_rbf,
            wr_ji + oHH, bi_ji + oH,
            wr_kj + oHH, bi_kj + oH,
            Wi_rbf1 + (size_t)b * R_DIM * BE_DIM,
            Wi_rbf2 + (size_t)b * BE_DIM * H_DIM,
            wr_down + (size_t)b * H_DIM * INT_DIM,
            (b == 0) ? Wo_rbf : nullptr, edge_i, (float4*)p_nodes,
            p_xji, p_xkjd, E);
        if (b == 0) run_output_mlp(0, 0);

        cudaMemsetAsync(p_agg, 0, (size_t)E * INT_DIM * sizeof(float));
        triplet_kernel<<<cdiv(T, 16), 256>>>(sb8Bufs[b],
            Wi_sbf2 + (size_t)b * BE_DIM * INT_DIM, p_xkjd, idx_kj, idx_ji,
            (float4*)p_agg, T);

        cudaMemsetAsync(p_nodes, 0, (size_t)Nn * H_DIM * sizeof(float));
        float* xeN = xeBufs[b];
        const float* wres = wr_res + (size_t)b * 3 * 2 * H_DIM * H_DIM;
        const float* bres = bi_res + (size_t)b * 3 * 2 * H_DIM;
        post_chain<<<nTiles, 256, SMEM_POST>>>(
            p_agg, p_xji, xe,
            wr_up + (size_t)b * INT_DIM * H_DIM,
            wres + 0 * H_DIM * H_DIM, bres + 0 * H_DIM,
            wres + 1 * H_DIM * H_DIM, bres + 1 * H_DIM,
            wr_lin + oHH, bi_lin + oH,
            wres + 2 * H_DIM * H_DIM, bres + 2 * H_DIM,
            wres + 3 * H_DIM * H_DIM, bres + 3 * H_DIM,
            wres + 4 * H_DIM * H_DIM, bres + 4 * H_DIM,
            wres + 5 * H_DIM * H_DIM, bres + 5 * H_DIM,
            p_rbf, Wo_rbf + (size_t)(b + 1) * R_DIM * H_DIM, edge_i,
            (float4*)p_nodes,
            xeN, E);
        xe = xeN;

        run_output_mlp(b + 1, 1);
    }
}

// round 16
// speedup vs baseline: 1.0946x; 1.0946x over previous
#include <cuda_runtime.h>
#include <cstdint>
#include <cstddef>

// ---------------------------------------------------------------------------
// DimeNet++ forward. Round 16: R14 chains (best numerics/perf) + node-MLP
// overlap on a side stream (graph fork/join via events) + double-buffered
// nodes accumulator.
// ---------------------------------------------------------------------------

#define E_MAX 120000
#define T_MAX 800000
#define N_MAX 12000
#define H_DIM 128
#define INT_DIM 64
#define BE_DIM 8
#define R_DIM 6
#define SR_DIM 42
#define OE_DIM 256

__device__ float g_rbf [E_MAX * R_DIM];
__device__ float g_xe1 [E_MAX * H_DIM];
__device__ float g_xe2 [E_MAX * H_DIM];
__device__ float g_xji [E_MAX * H_DIM];
__device__ float g_xkjd[E_MAX * INT_DIM];
__device__ float g_agg [E_MAX * INT_DIM];
__device__ float g_sb8a[T_MAX * BE_DIM];
__device__ float g_sb8b[T_MAX * BE_DIM];
__device__ float g_nodesA[N_MAX * H_DIM];
__device__ float g_nodesB[N_MAX * H_DIM];
__device__ float g_hn1 [N_MAX * OE_DIM];
__device__ float g_hn2 [N_MAX * OE_DIM];
__device__ float g_wr  [1015808];            // tf32-rounded weights

#define WR_KJ    0
#define WR_JI    32768
#define WR_DOWN  65536
#define WR_UP    81920
#define WR_RES   98304
#define WR_LIN   294912
#define WR_OUP   327680
#define WR_OLIN  425984

static inline int cdiv(int a, int b) { return (a + b - 1) / b; }

__device__ __forceinline__ float silu_f(float v) {
    return v / (1.0f + expf(-v));
}
__device__ __forceinline__ uint32_t f2tf32(float f) {
    uint32_t u;
    asm("cvt.rna.tf32.f32 %0, %1;" : "=r"(u) : "f"(f));
    return u;
}
__device__ __forceinline__ float roundtf(float f) {
    return __uint_as_float(f2tf32(f));
}

// ---------------- single-launch weight rounding ------------------------------
#define RND_SEGS 8
struct RndArgs {
    const float4* src[RND_SEGS];
    float4*       dst[RND_SEGS];
    int           n4[RND_SEGS];
};
__global__ void round_all_kernel(RndArgs a) {
    int seg = blockIdx.y;
    int i = blockIdx.x * blockDim.x + threadIdx.x;
    if (i >= a.n4[seg]) return;
    float4 v = a.src[seg][i];
    v.x = roundtf(v.x); v.y = roundtf(v.y);
    v.z = roundtf(v.z); v.w = roundtf(v.w);
    a.dst[seg][i] = v;
}

// ---------------- rbf ------------------------------------------------------
__global__ void rbf_kernel(const float* __restrict__ dist,
                           const float* __restrict__ freq,
                           float* __restrict__ rbf, int E) {
    int e = blockIdx.x * blockDim.x + threadIdx.x;
    if (e >= E) return;
    float d = dist[e] * (1.0f / 5.0f);
    float d2 = d * d;
    float d5 = d2 * d2 * d;
    float env = 1.0f / d - 28.0f * d5 + 48.0f * d5 * d - 21.0f * d5 * d2;
#pragma unroll
    for (int r = 0; r < R_DIM; r++)
        rbf[e * R_DIM + r] = env * sinf(freq[r] * d);
}

// ===========================================================================
// One GEMM stage over a resident 64-row smem tile (R14-proven config).
// A: smem fp32 [64 x K] stride sin (exact fp32; cvt.rna at fragment load).
// W: gmem tf32-rounded [K x N]; register-prefetch double-buffered.
// ===========================================================================
template <int K, int N>
__device__ __forceinline__ void run_mma(
    const float* tin, int sin,
    const float* Wg,
    float* wbuf,
    float acc[2][4][4], int tid)
{
    constexpr int NFRAG = N / 32;
    constexpr int WS    = N + 8;
    constexpr int WCH   = 32 * WS;
    constexpr int C     = K / 32;
    constexpr int WLD   = (32 * N) / 4 / 256;
    const int lane = tid & 31, warp = tid >> 5;
    const int gid = lane >> 2, tig = lane & 3;
    const int wm = (warp & 1) * 32, wn = (warp >> 1) * (N / 4);

#pragma unroll
    for (int i = 0; i < 2; i++)
#pragma unroll
        for (int j = 0; j < 4; j++)
#pragma unroll
            for (int l = 0; l < 4; l++) acc[i][j][l] = 0.0f;

    float4 pw[WLD];
#pragma unroll
    for (int i = 0; i < WLD; i++) {
        int idx = tid + i * 256;
        int n4 = idx & (N / 4 - 1);
        int kr = idx / (N / 4);
        pw[i] = *(const float4*)(Wg + (size_t)kr * N + n4 * 4);
    }

#pragma unroll
    for (int c = 0; c < C; c++) {
        float* buf = wbuf + (c & 1) * WCH;
#pragma unroll
        for (int i = 0; i < WLD; i++) {
            int idx = tid + i * 256;
            int n4 = idx & (N / 4 - 1);
            int kr = idx / (N / 4);
            *(float4*)&buf[kr * WS + n4 * 4] = pw[i];
        }
        __syncthreads();
        if (c + 1 < C) {
#pragma unroll
            for (int i = 0; i < WLD; i++) {
                int idx = tid + i * 256;
                int n4 = idx & (N / 4 - 1);
                int kr = idx / (N / 4);
                pw[i] = *(const float4*)(Wg + (size_t)((c + 1) * 32 + kr) * N + n4 * 4);
            }
        }

#pragma unroll
        for (int k8 = 0; k8 < 4; k8++) {
            const int col = c * 32 + k8 * 8 + tig;
            uint32_t af[2][4], bf[NFRAG][2];
#pragma unroll
            for (int mi = 0; mi < 2; mi++) {
                int r = wm + mi * 16 + gid;
                af[mi][0] = f2tf32(tin[(size_t)r * sin + col]);
                af[mi][1] = f2tf32(tin[(size_t)(r + 8) * sin + col]);
                af[mi][2] = f2tf32(tin[(size_t)r * sin + col + 4]);
                af[mi][3] = f2tf32(tin[(size_t)(r + 8) * sin + col + 4]);
            }
#pragma unroll
            for (int ni = 0; ni < NFRAG; ni++) {
                int nn = wn + ni * 8 + gid;
                bf[ni][0] = __float_as_uint(buf[(k8 * 8 + tig) * WS + nn]);
                bf[ni][1] = __float_as_uint(buf[(k8 * 8 + tig + 4) * WS + nn]);
            }
#pragma unroll
            for (int mi = 0; mi < 2; mi++)
#pragma unroll
                for (int ni = 0; ni < NFRAG; ni++)
                    asm volatile(
                        "mma.sync.aligned.m16n8k8.row.col.f32.tf32.tf32.f32 "
                        "{%0,%1,%2,%3}, {%4,%5,%6,%7}, {%8,%9}, {%0,%1,%2,%3};"
                        : "+f"(acc[mi][ni][0]), "+f"(acc[mi][ni][1]),
                          "+f"(acc[mi][ni][2]), "+f"(acc[mi][ni][3])
                        : "r"(af[mi][0]), "r"(af[mi][1]),
                          "r"(af[mi][2]), "r"(af[mi][3]),
                          "r"(bf[ni][0]), "r"(bf[ni][1]));
        }
    }
    __syncthreads();
}

// tile strides / smem offsets (fp32 words), BM=64
#define TS128 132
#define TS64  68
#define SM_TA 0
#define SM_TT 8448
#define SM_WB 16896
#define SM_T8 25600
#define SM_W2 26112
#define SM_WOR 27136
#define SMEM_PRE  (27904 * 4)
#define SMEM_POST (26368 * 4)

// epilogue iteration (variadic), BM=64
#define EPI_LOOP(NF, WN_SC, ...)                                               \
    {                                                                          \
        const int wm_ = (warp & 1) * 32;                                       \
        const int wn_ = (warp >> 1) * (WN_SC);                                 \
        _Pragma("unroll")                                                      \
        for (int mi = 0; mi < 2; mi++) {                                       \
            _Pragma("unroll")                                                  \
            for (int rr = 0; rr < 2; rr++) {                                   \
                const int ml = wm_ + mi * 16 + gid + rr * 8;                   \
                _Pragma("unroll")                                              \
                for (int ni = 0; ni < (NF); ni++) {                            \
                    const int n = wn_ + ni * 8 + tig * 2;                      \
                    float v0 = acc[mi][ni][rr * 2 + 0];                        \
                    float v1 = acc[mi][ni][rr * 2 + 1];                        \
                    __VA_ARGS__                                                \
                }                                                              \
            }                                                                  \
        }                                                                      \
    }

// gather from a smem tile (64 rows) into nodes via float4 atomics.
__device__ __forceinline__ void tile_gather(
    const float* tile, int ts, const float* wor,
    const float* __restrict__ rbf, const int* __restrict__ edge_i,
    float4* __restrict__ nodes, int bm, int E, int warp, int lane)
{
    for (int rr = warp; rr < 64; rr += 8) {
        int gm = bm + rr;
        if (gm >= E) continue;
        int ni = edge_i[gm];
        float rv[R_DIM];
#pragma unroll
        for (int r = 0; r < R_DIM; r++) rv[r] = rbf[gm * R_DIM + r];
        int c = lane * 4;
        float s0 = 0.f, s1 = 0.f, s2 = 0.f, s3 = 0.f;
#pragma unroll
        for (int r = 0; r < R_DIM; r++) {
            const float* w = wor + r * H_DIM + c;
            s0 += rv[r] * w[0];
            s1 += rv[r] * w[1];
            s2 += rv[r] * w[2];
            s3 += rv[r] * w[3];
        }
        const float* tv = tile + (size_t)rr * ts + c;
        float4 m = make_float4(s0 * tv[0], s1 * tv[1], s2 * tv[2], s3 * tv[3]);
        atomicAdd(&nodes[(size_t)ni * (H_DIM / 4) + lane], m);
    }
}

// ===========================================================================
// pre_chain — optional fused gather for output block 0
// ===========================================================================
__global__ __launch_bounds__(256)
void pre_chain(const float* __restrict__ xe, const float* __restrict__ rbf,
               const float* __restrict__ Wji, const float* __restrict__ bji,
               const float* __restrict__ Wkj, const float* __restrict__ bkj,
               const float* __restrict__ W1,  const float* __restrict__ W2,
               const float* __restrict__ Wdown,
               const float* __restrict__ Wo_r,
               const int* __restrict__ edge_i,
               float4* __restrict__ nodes,
               float* __restrict__ xji, float* __restrict__ xkjd, int E) {
    extern __shared__ float sm[];
    float* tileA = sm + SM_TA;
    float* tileT = sm + SM_TT;
    float* wbuf  = sm + SM_WB;
    float* t8    = sm + SM_T8;
    float* w2s   = sm + SM_W2;
    float* wor   = sm + SM_WOR;

    const int tid  = threadIdx.x;
    const int lane = tid & 31, warp = tid >> 5;
    const int gid  = lane >> 2, tig = lane & 3;
    const int bm   = blockIdx.x * 64;

#pragma unroll
    for (int i = 0; i < 8; i++) {
        int idx = tid + i * 256;
        int row = idx >> 5, c4 = idx & 31;
        int gm = bm + row;
        float4 v = (gm < E) ? *(const float4*)(xe + (size_t)gm * H_DIM + c4 * 4)
                            : make_float4(0.f, 0.f, 0.f, 0.f);
        *(float4*)&tileA[row * TS128 + c4 * 4] = v;
    }
    for (int i = tid; i < BE_DIM * H_DIM; i += 256) w2s[i] = W2[i];
    if (Wo_r) {
        for (int i = tid; i < R_DIM * H_DIM; i += 256) wor[i] = Wo_r[i];
    }
    if (tid < 64) {
        int gm = bm + tid;
        float rv[R_DIM];
#pragma unroll
        for (int r = 0; r < R_DIM; r++) rv[r] = (gm < E) ? rbf[gm * R_DIM + r] : 0.f;
#pragma unroll
        for (int j = 0; j < BE_DIM; j++) {
            float s = 0.f;
#pragma unroll
            for (int r = 0; r < R_DIM; r++) s += rv[r] * W1[r * BE_DIM + j];
            t8[tid * BE_DIM + j] = s;
        }
    }
    __syncthreads();

    if (Wo_r) {
        tile_gather(tileA, TS128, wor, rbf, edge_i, nodes, bm, E, warp, lane);
    }

    float acc[2][4][4];

    // S1: xji
    run_mma<128, 128>(tileA, TS128, Wji, wbuf, acc, tid);
    EPI_LOOP(4, 32, {
        int gm = bm + ml;
        if (gm < E) {
            v0 = silu_f(v0 + bji[n]);
            v1 = silu_f(v1 + bji[n + 1]);
            *(float2*)(xji + (size_t)gm * H_DIM + n) = make_float2(v0, v1);
        }
    })

    // S2: xk * rb -> tileT
    run_mma<128, 128>(tileA, TS128, Wkj, wbuf, acc, tid);
    EPI_LOOP(4, 32, {
        v0 = silu_f(v0 + bkj[n]);
        v1 = silu_f(v1 + bkj[n + 1]);
        float rb0 = 0.f;
        float rb1 = 0.f;
#pragma unroll
        for (int j = 0; j < BE_DIM; j++) {
            float tj = t8[ml * BE_DIM + j];
            rb0 += tj * w2s[j * H_DIM + n];
            rb1 += tj * w2s[j * H_DIM + n + 1];
        }
        tileT[ml * TS128 + n]     = v0 * rb0;
        tileT[ml * TS128 + n + 1] = v1 * rb1;
    })
    __syncthreads();

    // S3: xkjd
    run_mma<128, 64>(tileT, TS128, Wdown, wbuf, acc, tid);
    EPI_LOOP(2, 16, {
        int gm = bm + ml;
        if (gm < E) {
            v0 = silu_f(v0);
            v1 = silu_f(v1);
            *(float2*)(xkjd + (size_t)gm * INT_DIM + n) = make_float2(v0, v1);
        }
    })
}

// ===========================================================================
// post_chain — fused gather for next output block
// ===========================================================================
__global__ __launch_bounds__(256)
void post_chain(const float* __restrict__ agg, const float* __restrict__ xji,
                const float* __restrict__ xeOld,
                const float* __restrict__ Wup,
                const float* __restrict__ Wr0a, const float* __restrict__ br0a,
                const float* __restrict__ Wr0b, const float* __restrict__ br0b,
                const float* __restrict__ Wlin, const float* __restrict__ blin,
                const float* __restrict__ Wr1a, const float* __restrict__ br1a,
                const float* __restrict__ Wr1b, const float* __restrict__ br1b,
                const float* __restrict__ Wr2a, const float* __restrict__ br2a,
                const float* __restrict__ Wr2b, const float* __restrict__ br2b,
                const float* __restrict__ rbfp,
                const float* __restrict__ Wo_r,
                const int* __restrict__ edge_i,
                float4* __restrict__ nodes,
                float* __restrict__ xeNew, int E) {
    extern __shared__ float sm[];
    float* tileA = sm + SM_TA;
    float* tileT = sm + SM_TT;
    float* wbuf  = sm + SM_WB;
    float* wor   = sm + SM_T8;

    const int tid  = threadIdx.x;
    const int lane = tid & 31, warp = tid >> 5;
    const int gid  = lane >> 2, tig = lane & 3;
    const int bm   = blockIdx.x * 64;

#pragma unroll
    for (int i = 0; i < 4; i++) {
        int idx = tid + i * 256;
        int row = idx >> 4, c4 = idx & 15;
        int gm = bm + row;
        float4 v = (gm < E) ? *(const float4*)(agg + (size_t)gm * INT_DIM + c4 * 4)
                            : make_float4(0.f, 0.f, 0.f, 0.f);
        *(float4*)&tileT[row * TS64 + c4 * 4] = v;
    }
    for (int i = tid; i < R_DIM * H_DIM; i += 256) wor[i] = Wo_r[i];
    __syncthreads();

    float acc[2][4][4];

    // up
    run_mma<64, 128>(tileT, TS64, Wup, wbuf, acc, tid);
    EPI_LOOP(4, 32, {
        int gm = bm + ml;
        float2 p = (gm < E) ? *(const float2*)(xji + (size_t)gm * H_DIM + n)
                            : make_float2(0.f, 0.f);
        tileA[ml * TS128 + n]     = p.x + silu_f(v0);
        tileA[ml * TS128 + n + 1] = p.y + silu_f(v1);
    })
    __syncthreads();

    // res0a
    run_mma<128, 128>(tileA, TS128, Wr0a, wbuf, acc, tid);
    EPI_LOOP(4, 32, {
        tileT[ml * TS128 + n]     = silu_f(v0 + br0a[n]);
        tileT[ml * TS128 + n + 1] = silu_f(v1 + br0a[n + 1]);
    })
    __syncthreads();

    // res0b
    run_mma<128, 128>(tileT, TS128, Wr0b, wbuf, acc, tid);
    EPI_LOOP(4, 32, {
        tileA[ml * TS128 + n]     += silu_f(v0 + br0b[n]);
        tileA[ml * TS128 + n + 1] += silu_f(v1 + br0b[n + 1]);
    })
    __syncthreads();

    // lin+skip
    run_mma<128, 128>(tileA, TS128, Wlin, wbuf, acc, tid);
    EPI_LOOP(4, 32, {
        int gm = bm + ml;
        float2 p = (gm < E) ? *(const float2*)(xeOld + (size_t)gm * H_DIM + n)
                            : make_float2(0.f, 0.f);
        tileT[ml * TS128 + n]     = silu_f(v0 + blin[n]) + p.x;
        tileT[ml * TS128 + n + 1] = silu_f(v1 + blin[n + 1]) + p.y;
    })
    __syncthreads();

    // res1a
    run_mma<128, 128>(tileT, TS128, Wr1a, wbuf, acc, tid);
    EPI_LOOP(4, 32, {
        tileA[ml * TS128 + n]     = silu_f(v0 + br1a[n]);
        tileA[ml * TS128 + n + 1] = silu_f(v1 + br1a[n + 1]);
    })
    __syncthreads();

    // res1b
    run_mma<128, 128>(tileA, TS128, Wr1b, wbuf, acc, tid);
    EPI_LOOP(4, 32, {
        tileT[ml * TS128 + n]     += silu_f(v0 + br1b[n]);
        tileT[ml * TS128 + n + 1] += silu_f(v1 + br1b[n + 1]);
    })
    __syncthreads();

    // res2a
    run_mma<128, 128>(tileT, TS128, Wr2a, wbuf, acc, tid);
    EPI_LOOP(4, 32, {
        tileA[ml * TS128 + n]     = silu_f(v0 + br2a[n]);
        tileA[ml * TS128 + n + 1] = silu_f(v1 + br2a[n + 1]);
    })
    __syncthreads();

    // res2b -> xeNew (gmem) and tileT (for fused gather)
    run_mma<128, 128>(tileA, TS128, Wr2b, wbuf, acc, tid);
    EPI_LOOP(4, 32, {
        int gm = bm + ml;
        v0 = tileT[ml * TS128 + n]     + silu_f(v0 + br2b[n]);
        v1 = tileT[ml * TS128 + n + 1] + silu_f(v1 + br2b[n + 1]);
        tileT[ml * TS128 + n]     = v0;
        tileT[ml * TS128 + n + 1] = v1;
        if (gm < E) {
            *(float2*)(xeNew + (size_t)gm * H_DIM + n) = make_float2(v0, v1);
        }
    })
    __syncthreads();

    tile_gather(tileT, TS128, wor, rbfp, edge_i, nodes, bm, E, warp, lane);
}

// ---------------- tf32 GEMM (node path), cp.async pipeline ------------------
#define TBM 128
#define TBK 32

template <int BN_, bool SILU>
__global__ __launch_bounds__(256, 2)
void tgemm(const float* __restrict__ A, const float* __restrict__ W,
           const float* __restrict__ bias,
           float* __restrict__ C, int M, int K, int N) {
    constexpr int NFRAG   = BN_ / 32;
    constexpr int WSTRIDE = BN_ + 8;
    constexpr int ASZ     = TBM * 36;
    constexpr int WSZ     = TBK * WSTRIDE;
    constexpr int WLD     = (TBK * BN_) / 4 / 256;

    extern __shared__ uint32_t smw[];
    const uint32_t smem_u32 = (uint32_t)__cvta_generic_to_shared(smw);

    const int bm   = blockIdx.y * TBM;
    const int bn   = blockIdx.x * BN_;
    const int tid  = threadIdx.x;
    const int lane = tid & 31;
    const int warp = tid >> 5;
    const int gid  = lane >> 2;
    const int tig  = lane & 3;
    const int wm   = (warp & 1) * 64;
    const int wn   = (warp >> 1) * (BN_ / 4);

    float acc[4][NFRAG][4];
#pragma unroll
    for (int i = 0; i < 4; i++)
#pragma unroll
        for (int j = 0; j < NFRAG; j++)
#pragma unroll
            for (int l = 0; l < 4; l++) acc[i][j][l] = 0.0f;

    const int nk = K / TBK;

#define ISSUE(KT, S)                                                            \
    {                                                                           \
        _Pragma("unroll")                                                       \
        for (int i = 0; i < 4; i++) {                                           \
            int idx = tid + i * 256;                                            \
            int row = idx >> 3, c4 = idx & 7;                                   \
            int gm = bm + row;                                                  \
            int ok = (gm < M);                                                  \
            const float* src = A + (size_t)(ok ? gm : 0) * K + (KT) * TBK + c4 * 4; \
            uint32_t dst = smem_u32 + ((S) * ASZ + row * 36 + c4 * 4) * 4;      \
            int p = ok ? 16 : 0;                                                \
            asm volatile("cp.async.cg.shared.global [%0], [%1], 16, %2;\n"      \
                         :: "r"(dst), "l"(src), "r"(p));                        \
        }                                                                       \
        _Pragma("unroll")                                                       \
        for (int i = 0; i < WLD; i++) {                                         \
            int idx = tid + i * 256;                                            \
            int c4 = idx & (BN_ / 4 - 1);                                       \
            int kr = idx / (BN_ / 4);                                           \
            const float* src = W + (size_t)((KT) * TBK + kr) * N + bn + c4 * 4; \
            uint32_t dst = smem_u32 + (2 * ASZ + (S) * WSZ + kr * WSTRIDE + c4 * 4) * 4; \
            asm volatile("cp.async.cg.shared.global [%0], [%1], 16;\n"          \
                         :: "r"(dst), "l"(src));                                \
        }                                                                       \
        asm volatile("cp.async.commit_group;\n" ::: "memory");                  \
    }

    ISSUE(0, 0);

    for (int kt = 0; kt < nk; kt++) {
        const int cur = kt & 1;
        if (kt + 1 < nk) {
            ISSUE(kt + 1, (kt + 1) & 1);
            asm volatile("cp.async.wait_group 1;\n" ::: "memory");
        } else {
            asm volatile("cp.async.wait_group 0;\n" ::: "memory");
        }
        __syncthreads();

        const uint32_t* Ab = smw + cur * ASZ;
        const uint32_t* Wb = smw + 2 * ASZ + cur * WSZ;
#pragma unroll
        for (int k8 = 0; k8 < TBK / 8; k8++) {
            uint32_t af[4][4], bf[NFRAG][2];
#pragma unroll
            for (int mi = 0; mi < 4; mi++) {
                int r = wm + mi * 16 + gid;
                af[mi][0] = f2tf32(__uint_as_float(Ab[(size_t)r * 36 + k8 * 8 + tig]));
                af[mi][1] = f2tf32(__uint_as_float(Ab[(size_t)(r + 8) * 36 + k8 * 8 + tig]));
                af[mi][2] = f2tf32(__uint_as_float(Ab[(size_t)r * 36 + k8 * 8 + tig + 4]));
                af[mi][3] = f2tf32(__uint_as_float(Ab[(size_t)(r + 8) * 36 + k8 * 8 + tig + 4]));
            }
#pragma unroll
            for (int ni = 0; ni < NFRAG; ni++) {
                int n = wn + ni * 8 + gid;
                bf[ni][0] = Wb[(size_t)(k8 * 8 + tig) * WSTRIDE + n];
                bf[ni][1] = Wb[(size_t)(k8 * 8 + tig + 4) * WSTRIDE + n];
            }
#pragma unroll
            for (int mi = 0; mi < 4; mi++)
#pragma unroll
                for (int ni = 0; ni < NFRAG; ni++)
                    asm volatile(
                        "mma.sync.aligned.m16n8k8.row.col.f32.tf32.tf32.f32 "
                        "{%0,%1,%2,%3}, {%4,%5,%6,%7}, {%8,%9}, {%0,%1,%2,%3};"
                        : "+f"(acc[mi][ni][0]), "+f"(acc[mi][ni][1]),
                          "+f"(acc[mi][ni][2]), "+f"(acc[mi][ni][3])
                        : "r"(af[mi][0]), "r"(af[mi][1]),
                          "r"(af[mi][2]), "r"(af[mi][3]),
                          "r"(bf[ni][0]), "r"(bf[ni][1]));
        }
        __syncthreads();
    }

#pragma unroll
    for (int mi = 0; mi < 4; mi++) {
#pragma unroll
        for (int rr = 0; rr < 2; rr++) {
            int m = bm + wm + mi * 16 + gid + rr * 8;
            if (m >= M) continue;
#pragma unroll
            for (int ni = 0; ni < NFRAG; ni++) {
                int n = bn + wn + ni * 8 + tig * 2;
                float v0 = acc[mi][ni][rr * 2 + 0];
                float v1 = acc[mi][ni][rr * 2 + 1];
                if (bias) { v0 += bias[n]; v1 += bias[n + 1]; }
                if (SILU) { v0 = silu_f(v0); v1 = silu_f(v1); }
                *(float2*)(C + (size_t)m * N + n) = make_float2(v0, v1);
            }
        }
    }
#undef ISSUE
}

#define SMEM_T128 ((2 * TBM * 36 + 2 * TBK * (128 + 8)) * 4)

// ---------------- dual sb8 --------------------------------------------------
__global__ void sb8_dual_kernel(const float* __restrict__ sbf,
                                const float* __restrict__ W1a,
                                const float* __restrict__ W1b,
                                float* __restrict__ sb8a,
                                float* __restrict__ sb8b, int T) {
    __shared__ float Wa[SR_DIM * BE_DIM];
    __shared__ float Wb[SR_DIM * BE_DIM];
    for (int i = threadIdx.x; i < SR_DIM * BE_DIM; i += blockDim.x) {
        Wa[i] = W1a[i];
        Wb[i] = W1b[i];
    }
    __syncthreads();
    int t = blockIdx.x * blockDim.x + threadIdx.x;
    if (t >= T) return;
    const float2* row = (const float2*)(sbf + (size_t)t * SR_DIM);
    float ta[BE_DIM] = {};
    float tb[BE_DIM] = {};
#pragma unroll
    for (int r2 = 0; r2 < SR_DIM / 2; r2++) {
        float2 v = row[r2];
        int r = r2 * 2;
#pragma unroll
        for (int j = 0; j < BE_DIM; j++) {
            ta[j] += v.x * Wa[r * BE_DIM + j] + v.y * Wa[(r + 1) * BE_DIM + j];
            tb[j] += v.x * Wb[r * BE_DIM + j] + v.y * Wb[(r + 1) * BE_DIM + j];
        }
    }
    float4* oa = (float4*)(sb8a + (size_t)t * BE_DIM);
    oa[0] = make_float4(ta[0], ta[1], ta[2], ta[3]);
    oa[1] = make_float4(ta[4], ta[5], ta[6], ta[7]);
    float4* ob = (float4*)(sb8b + (size_t)t * BE_DIM);
    ob[0] = make_float4(tb[0], tb[1], tb[2], tb[3]);
    ob[1] = make_float4(tb[4], tb[5], tb[6], tb[7]);
}

// ---------------- triplet scatter ------------------------------------------
__global__ void triplet_kernel(const float* __restrict__ sb8,
                               const float* __restrict__ W2,
                               const float* __restrict__ xkd,
                               const int* __restrict__ idx_kj,
                               const int* __restrict__ idx_ji,
                               float4* __restrict__ agg, int T) {
    __shared__ float W2s[BE_DIM * INT_DIM];
    for (int i = threadIdx.x; i < BE_DIM * INT_DIM; i += blockDim.x) W2s[i] = W2[i];
    __syncthreads();
    int warp = threadIdx.x >> 5, lane = threadIdx.x & 31;
    int t = (blockIdx.x * (blockDim.x >> 5) + warp) * 2 + (lane >> 4);
    if (t >= T) return;
    int l16 = lane & 15;
    int ik = idx_kj[t];
    int ij = idx_ji[t];
    float4 sA = *(const float4*)(sb8 + (size_t)t * BE_DIM);
    float4 sB = *(const float4*)(sb8 + (size_t)t * BE_DIM + 4);
    float sv[8] = {sA.x, sA.y, sA.z, sA.w, sB.x, sB.y, sB.z, sB.w};
    float4 v = make_float4(0.f, 0.f, 0.f, 0.f);
#pragma unroll
    for (int i = 0; i < BE_DIM; i++) {
        const float* wrow = W2s + i * INT_DIM + l16 * 4;
        v.x += sv[i] * wrow[0];
        v.y += sv[i] * wrow[1];
        v.z += sv[i] * wrow[2];
        v.w += sv[i] * wrow[3];
    }
    float4 x = *(const float4*)(xkd + (size_t)ik * INT_DIM + l16 * 4);
    float4 m = make_float4(x.x * v.x, x.y * v.y, x.z * v.z, x.w * v.w);
    atomicAdd(&agg[(size_t)ij * (INT_DIM / 4) + l16], m);
}

// ---------------- final projection -----------------------------------------
__global__ void out_final_kernel(const float* __restrict__ hn,
                                 const float* __restrict__ Wout,
                                 float* __restrict__ out, int Nn, int accumulate) {
    int warp = threadIdx.x >> 5, lane = threadIdx.x & 31;
    int n = blockIdx.x * (blockDim.x >> 5) + warp;
    if (n >= Nn) return;
    float s = 0.0f;
#pragma unroll
    for (int k = lane; k < OE_DIM; k += 32) s += hn[(size_t)n * OE_DIM + k] * Wout[k];
#pragma unroll
    for (int o = 16; o > 0; o >>= 1) s += __shfl_xor_sync(0xffffffffu, s, o);
    if (lane == 0) {
        if (accumulate) out[n] += s;
        else            out[n] = s;
    }
}

// ---------------------------------------------------------------------------
extern "C" void kernel_launch(void* const* d_in, const int* in_sizes, int n_in,
                              void* d_out, int out_size) {
    const float* x       = (const float*)d_in[0];
    const float* dist    = (const float*)d_in[1];
    const float* freq    = (const float*)d_in[2];
    const float* sbf     = (const float*)d_in[3];
    const int*   idx_kj  = (const int*)d_in[4];
    const int*   idx_ji  = (const int*)d_in[5];
    const int*   edge_i  = (const int*)d_in[6];
    const float* Wi_rbf1 = (const float*)d_in[8];
    const float* Wi_rbf2 = (const float*)d_in[9];
    const float* Wi_sbf1 = (const float*)d_in[10];
    const float* Wi_sbf2 = (const float*)d_in[11];
    const float* Wi_kj   = (const float*)d_in[12];
    const float* bi_kj   = (const float*)d_in[13];
    const float* Wi_ji   = (const float*)d_in[14];
    const float* bi_ji   = (const float*)d_in[15];
    const float* Wi_down = (const float*)d_in[16];
    const float* Wi_up   = (const float*)d_in[17];
    const float* Wi_res  = (const float*)d_in[18];
    const float* bi_res  = (const float*)d_in[19];
    const float* Wi_lin  = (const float*)d_in[20];
    const float* bi_lin  = (const float*)d_in[21];
    const float* Wo_rbf  = (const float*)d_in[22];
    const float* Wo_up   = (const float*)d_in[23];
    const float* bo_up   = (const float*)d_in[24];
    const float* Wo_lin  = (const float*)d_in[25];
    const float* bo_lin  = (const float*)d_in[26];
    const float* Wo_out  = (const float*)d_in[27];

    const int E  = in_sizes[1];
    const int T  = in_sizes[4];
    const int Nn = out_size;
    float* out = (float*)d_out;

    float *p_rbf, *p_xe1, *p_xe2, *p_xji, *p_xkjd, *p_agg, *p_sb8a, *p_sb8b;
    float *p_nodesA, *p_nodesB, *p_hn1, *p_hn2, *p_wr;
    cudaGetSymbolAddress((void**)&p_rbf,   g_rbf);
    cudaGetSymbolAddress((void**)&p_xe1,   g_xe1);
    cudaGetSymbolAddress((void**)&p_xe2,   g_xe2);
    cudaGetSymbolAddress((void**)&p_xji,   g_xji);
    cudaGetSymbolAddress((void**)&p_xkjd,  g_xkjd);
    cudaGetSymbolAddress((void**)&p_agg,   g_agg);
    cudaGetSymbolAddress((void**)&p_sb8a,  g_sb8a);
    cudaGetSymbolAddress((void**)&p_sb8b,  g_sb8b);
    cudaGetSymbolAddress((void**)&p_nodesA,g_nodesA);
    cudaGetSymbolAddress((void**)&p_nodesB,g_nodesB);
    cudaGetSymbolAddress((void**)&p_hn1,   g_hn1);
    cudaGetSymbolAddress((void**)&p_hn2,   g_hn2);
    cudaGetSymbolAddress((void**)&p_wr,    g_wr);

    cudaFuncSetAttribute(pre_chain,  cudaFuncAttributeMaxDynamicSharedMemorySize, SMEM_PRE);
    cudaFuncSetAttribute(post_chain, cudaFuncAttributeMaxDynamicSharedMemorySize, SMEM_POST);
    cudaFuncSetAttribute(tgemm<128, true >, cudaFuncAttributeMaxDynamicSharedMemorySize, SMEM_T128);
    cudaFuncSetAttribute(tgemm<128, false>, cudaFuncAttributeMaxDynamicSharedMemorySize, SMEM_T128);

    // side stream + events for node-MLP overlap (created once, outside capture:
    // the harness's first call is the un-captured correctness run)
    static cudaStream_t s_side = nullptr;
    static cudaEvent_t  s_ev[5];
    if (!s_side) {
        cudaStreamCreateWithFlags(&s_side, cudaStreamNonBlocking);
        for (int i = 0; i < 5; i++)
            cudaEventCreateWithFlags(&s_ev[i], cudaEventDisableTiming);
    }
    cudaEvent_t evPre0 = s_ev[0], evM0 = s_ev[1], evPost0 = s_ev[2];
    cudaEvent_t evPost1 = s_ev[3], evM2 = s_ev[4];

    // ---- single-launch weight rounding ----
    RndArgs ra;
    const float* srcs[RND_SEGS] = {Wi_kj, Wi_ji, Wi_down, Wi_up, Wi_res, Wi_lin, Wo_up, Wo_lin};
    const int    offs[RND_SEGS] = {WR_KJ, WR_JI, WR_DOWN, WR_UP, WR_RES, WR_LIN, WR_OUP, WR_OLIN};
    const int    cnts[RND_SEGS] = {
        2 * H_DIM * H_DIM, 2 * H_DIM * H_DIM, 2 * H_DIM * INT_DIM,
        2 * INT_DIM * H_DIM, 2 * 3 * 2 * H_DIM * H_DIM, 2 * H_DIM * H_DIM,
        3 * H_DIM * OE_DIM, 3 * 3 * OE_DIM * OE_DIM};
    int max_n4 = 0;
    for (int s = 0; s < RND_SEGS; s++) {
        ra.src[s] = (const float4*)srcs[s];
        ra.dst[s] = (float4*)(p_wr + offs[s]);
        ra.n4[s]  = cnts[s] / 4;
        if (ra.n4[s] > max_n4) max_n4 = ra.n4[s];
    }
    round_all_kernel<<<dim3(cdiv(max_n4, 256), RND_SEGS), 256>>>(ra);

    const float* wr_kj   = p_wr + WR_KJ;
    const float* wr_ji   = p_wr + WR_JI;
    const float* wr_down = p_wr + WR_DOWN;
    const float* wr_up   = p_wr + WR_UP;
    const float* wr_res  = p_wr + WR_RES;
    const float* wr_lin  = p_wr + WR_LIN;
    const float* wr_oup  = p_wr + WR_OUP;
    const float* wr_olin = p_wr + WR_OLIN;

    const int nTiles = cdiv(E, 64);
    const dim3 gN256(OE_DIM / 128, cdiv(Nn, TBM));

    rbf_kernel<<<cdiv(E, 256), 256>>>(dist, freq, p_rbf, E);
    sb8_dual_kernel<<<cdiv(T, 256), 256>>>(sbf,
        Wi_sbf1, Wi_sbf1 + (size_t)SR_DIM * BE_DIM, p_sb8a, p_sb8b, T);

    // MLP part of an output block on a given stream; nodes already populated.
    auto run_output_mlp = [&](int b, int acc, const float* nodes, cudaStream_t st) {
        tgemm<128, false><<<gN256, 256, SMEM_T128, st>>>(
            nodes, wr_oup + (size_t)b * H_DIM * OE_DIM, bo_up + (size_t)b * OE_DIM,
            p_hn1, Nn, H_DIM, OE_DIM);
        for (int l = 0; l < 3; l++) {
            const float* src = (l & 1) ? p_hn2 : p_hn1;
            float*       dst = (l & 1) ? p_hn1 : p_hn2;
            tgemm<128, true><<<gN256, 256, SMEM_T128, st>>>(
                src, wr_olin + ((size_t)b * 3 + l) * OE_DIM * OE_DIM,
                bo_lin + ((size_t)b * 3 + l) * OE_DIM, dst, Nn, OE_DIM, OE_DIM);
        }
        out_final_kernel<<<cdiv(Nn, 8), 256, 0, st>>>(
            p_hn2, Wo_out + (size_t)b * OE_DIM, out, Nn, acc);
    };

    // ===== block b = 0 =====
    cudaMemsetAsync(p_nodesA, 0, (size_t)Nn * H_DIM * sizeof(float));
    pre_chain<<<nTiles, 256, SMEM_PRE>>>(
        x, p_rbf,
        wr_ji, bi_ji, wr_kj, bi_kj,
        Wi_rbf1, Wi_rbf2, wr_down,
        Wo_rbf, edge_i, (float4*)p_nodesA,
        p_xji, p_xkjd, E);
    cudaEventRecord(evPre0, 0);
    cudaStreamWaitEvent(s_side, evPre0, 0);
    run_output_mlp(0, 0, p_nodesA, s_side);           // P = output_block(0, x)
    cudaEventRecord(evM0, s_side);

    cudaMemsetAsync(p_agg, 0, (size_t)E * INT_DIM * sizeof(float));
    triplet_kernel<<<cdiv(T, 16), 256>>>(p_sb8a,
        Wi_sbf2, p_xkjd, idx_kj, idx_ji, (float4*)p_agg, T);

    cudaMemsetAsync(p_nodesB, 0, (size_t)Nn * H_DIM * sizeof(float));
    {
        const float* wres = wr_res;
        const float* bres = bi_res;
        post_chain<<<nTiles, 256, SMEM_POST>>>(
            p_agg, p_xji, x,
            wr_up,
            wres + 0 * H_DIM * H_DIM, bres + 0 * H_DIM,
            wres + 1 * H_DIM * H_DIM, bres + 1 * H_DIM,
            wr_lin, bi_lin,
            wres + 2 * H_DIM * H_DIM, bres + 2 * H_DIM,
            wres + 3 * H_DIM * H_DIM, bres + 3 * H_DIM,
            wres + 4 * H_DIM * H_DIM, bres + 4 * H_DIM,
            wres + 5 * H_DIM * H_DIM, bres + 5 * H_DIM,
            p_rbf, Wo_rbf + (size_t)1 * R_DIM * H_DIM, edge_i,
            (float4*)p_nodesB,
            p_xe1, E);
    }
    cudaEventRecord(evPost0, 0);
    cudaStreamWaitEvent(s_side, evPost0, 0);
    run_output_mlp(1, 1, p_nodesB, s_side);           // P += output_block(1, xe1)

    // ===== block b = 1 =====
    pre_chain<<<nTiles, 256, SMEM_PRE>>>(
        p_xe1, p_rbf,
        wr_ji + (size_t)H_DIM * H_DIM, bi_ji + H_DIM,
        wr_kj + (size_t)H_DIM * H_DIM, bi_kj + H_DIM,
        Wi_rbf1 + (size_t)R_DIM * BE_DIM,
        Wi_rbf2 + (size_t)BE_DIM * H_DIM,
        wr_down + (size_t)H_DIM * INT_DIM,
        nullptr, edge_i, (float4*)p_nodesA,
        p_xji, p_xkjd, E);

    cudaMemsetAsync(p_agg, 0, (size_t)E * INT_DIM * sizeof(float));
    triplet_kernel<<<cdiv(T, 16), 256>>>(p_sb8b,
        Wi_sbf2 + (size_t)BE_DIM * INT_DIM, p_xkjd, idx_kj, idx_ji,
        (float4*)p_agg, T);

    cudaStreamWaitEvent(0, evM0, 0);                  // nodesA free after MLP(0)
    cudaMemsetAsync(p_nodesA, 0, (size_t)Nn * H_DIM * sizeof(float));
    {
        const float* wres = wr_res + (size_t)3 * 2 * H_DIM * H_DIM;
        const float* bres = bi_res + (size_t)3 * 2 * H_DIM;
        post_chain<<<nTiles, 256, SMEM_POST>>>(
            p_agg, p_xji, p_xe1,
            wr_up + (size_t)INT_DIM * H_DIM,
            wres + 0 * H_DIM * H_DIM, bres + 0 * H_DIM,
            wres + 1 * H_DIM * H_DIM, bres + 1 * H_DIM,
            wr_lin + (size_t)H_DIM * H_DIM, bi_lin + H_DIM,
            wres + 2 * H_DIM * H_DIM, bres + 2 * H_DIM,
            wres + 3 * H_DIM * H_DIM, bres + 3 * H_DIM,
            wres + 4 * H_DIM * H_DIM, bres + 4 * H_DIM,
            wres + 5 * H_DIM * H_DIM, bres + 5 * H_DIM,
            p_rbf, Wo_rbf + (size_t)2 * R_DIM * H_DIM, edge_i,
            (float4*)p_nodesA,
            p_xe2, E);
    }
    cudaEventRecord(evPost1, 0);
    cudaStreamWaitEvent(s_side, evPost1, 0);
    run_output_mlp(2, 1, p_nodesA, s_side);           // P += output_block(2, xe2)
    cudaEventRecord(evM2, s_side);
    cudaStreamWaitEvent(0, evM2, 0);                  // join side stream
}